// round 8
// baseline (speedup 1.0000x reference)
#include <cuda_runtime.h>
#include <math.h>

// MS-SSIM 3D, 5 levels, separable 11-tap Gaussian conv.
// Inputs: d_in[0]=img1 (2,1,192,192,192) f32, d_in[1]=img2 same. Output: 1 f32 scalar.

struct W11 { float w[11]; };

#define NLVL 5
#define ZB 4
#define YB 4

__device__ double   g_ssim_sum[NLVL];
__device__ double   g_cs_sum[NLVL];
__device__ unsigned g_min_enc[NLVL];
__device__ unsigned g_max_enc[NLVL];

#define S1MAX (2*192*192*182)   // elements per field after x-conv
#define S2MAX (2*192*182*182)   // elements per field after y-conv
#define POOLSZ (2*96*96*96)

__device__ __align__(16) float g_T1[5ull * S1MAX];
__device__ __align__(16) float g_T2[5ull * S2MAX];
__device__ __align__(16) float g_poolA[2ull * POOLSZ];
__device__ __align__(16) float g_poolB[2ull * POOLSZ];

__device__ __forceinline__ unsigned enc_f(float f) {
    unsigned u = __float_as_uint(f);
    return (u & 0x80000000u) ? ~u : (u | 0x80000000u);
}
__device__ __forceinline__ float dec_f(unsigned e) {
    unsigned u = (e & 0x80000000u) ? (e & 0x7FFFFFFFu) : ~e;
    return __uint_as_float(u);
}

__global__ void init_kernel() {
    int i = threadIdx.x;
    if (i < NLVL) {
        g_ssim_sum[i] = 0.0;
        g_cs_sum[i]   = 0.0;
        g_min_enc[i]  = 0xFFFFFFFFu;
        g_max_enc[i]  = 0u;
    }
}

// x-direction conv; builds all 5 fields (a, b, a*a, b*b, a*b) on the fly.
// Also folds the img1 min/max reduction (for L) into this pass.
__global__ void pass1_kernel(const float* __restrict__ A, const float* __restrict__ B,
                             int D, int lvl, W11 wt) {
    const int W = D, Wm = W - 10;
    const int row = blockIdx.x;
    __shared__ float sa[192], sb[192];
    const int tx = threadIdx.x;
    const float* a = A + (size_t)row * W;
    const float* b = B + (size_t)row * W;
    float av = 0.f;
    bool in_row = (tx < W);
    if (in_row) { av = a[tx]; sa[tx] = av; sb[tx] = b[tx]; }
    __syncthreads();

    // --- min/max reduction of A over this row ---
    unsigned mn = in_row ? enc_f(av) : 0xFFFFFFFFu;
    unsigned mx = in_row ? enc_f(av) : 0u;
#pragma unroll
    for (int o = 16; o; o >>= 1) {
        mn = min(mn, __shfl_xor_sync(0xFFFFFFFFu, mn, o));
        mx = max(mx, __shfl_xor_sync(0xFFFFFFFFu, mx, o));
    }
    __shared__ unsigned smn[6], smx[6];
    int wid = tx >> 5;
    if ((tx & 31) == 0) { smn[wid] = mn; smx[wid] = mx; }
    __syncthreads();
    if (tx == 0) {
        int nw = (blockDim.x + 31) >> 5;
        for (int i = 1; i < nw; i++) { mn = min(mn, smn[i]); mx = max(mx, smx[i]); }
        atomicMin(&g_min_enc[lvl], mn);
        atomicMax(&g_max_enc[lvl], mx);
    }

    // --- x-conv ---
    if (tx < Wm) {
        float s1 = 0.f, s2 = 0.f, s11 = 0.f, s22 = 0.f, s12 = 0.f;
#pragma unroll
        for (int k = 0; k < 11; k++) {
            float w = wt.w[k], x = sa[tx + k], y = sb[tx + k];
            s1  = fmaf(w, x, s1);
            s2  = fmaf(w, y, s2);
            float wx = w * x;
            s11 = fmaf(wx, x, s11);
            s12 = fmaf(wx, y, s12);
            s22 = fmaf(w * y, y, s22);
        }
        size_t S1 = (size_t)2 * D * D * Wm;
        size_t o  = (size_t)row * Wm + tx;
        g_T1[o]          = s1;
        g_T1[S1 + o]     = s2;
        g_T1[2 * S1 + o] = s11;
        g_T1[3 * S1 + o] = s22;
        g_T1[4 * S1 + o] = s12;
    }
}

// y-direction conv, float2 vectorized, YB-blocked: each thread computes YB
// consecutive y outputs, loading YB+10 input rows once instead of 11 per output.
__global__ void pass2_kernel(int D, W11 wt) {
    const int Wm = D - 10, Hm = D - 10, Wmv = Wm >> 1;
    const int nyb = (Hm + YB - 1) / YB;
    const size_t S1v = ((size_t)2 * D * D * Wm) >> 1;
    const size_t S2v = ((size_t)2 * D * Hm * Wm) >> 1;
    const size_t total = (size_t)2 * D * nyb * Wmv;
    size_t idx = (size_t)blockIdx.x * blockDim.x + threadIdx.x;
    if (idx >= total) return;
    int xv = (int)(idx % Wmv);
    size_t t = idx / Wmv;
    int yb = (int)(t % nyb);
    int zn = (int)(t / nyb);           // 0 .. 2*D-1 (n*D + z)
    int y0 = yb * YB;
    const float2* in  = (const float2*)g_T1;
    float2*       out = (float2*)g_T2;
    size_t ib = ((size_t)zn * D + y0) * Wmv + xv;

    float2 acc[5][YB];
#pragma unroll
    for (int f = 0; f < 5; f++)
#pragma unroll
        for (int j = 0; j < YB; j++) acc[f][j] = make_float2(0.f, 0.f);

#pragma unroll
    for (int k = 0; k < YB + 10; k++) {
        if (y0 + k < D) {
            float2 v[5];
#pragma unroll
            for (int f = 0; f < 5; f++) v[f] = in[f * S1v + ib + (size_t)k * Wmv];
#pragma unroll
            for (int j = 0; j < YB; j++) {
                int ki = k - j;
                if (ki >= 0 && ki < 11) {
                    float w = wt.w[ki];
#pragma unroll
                    for (int f = 0; f < 5; f++) {
                        acc[f][j].x = fmaf(w, v[f].x, acc[f][j].x);
                        acc[f][j].y = fmaf(w, v[f].y, acc[f][j].y);
                    }
                }
            }
        }
    }

#pragma unroll
    for (int j = 0; j < YB; j++) {
        if (y0 + j < Hm) {
            size_t ob = ((size_t)zn * Hm + (y0 + j)) * Wmv + xv;
#pragma unroll
            for (int f = 0; f < 5; f++) out[f * S2v + ob] = acc[f][j];
        }
    }
}

__device__ __forceinline__ void ssim_eval(float m1, float m2, float q11, float q22, float q12,
                                          float C1, float C2, float& cs_acc, float& ss_acc) {
    float mu11 = m1 * m1, mu22 = m2 * m2, mu12 = m1 * m2;
    float sg1 = q11 - mu11, sg2 = q22 - mu22, sg12 = q12 - mu12;
    float v1 = 2.f * sg12 + C2;
    float v2 = sg1 + sg2 + C2;
    cs_acc += v1 / v2;
    ss_acc += ((2.f * mu12 + C1) * v1) / ((mu11 + mu22 + C1) * v2);
}

// z-direction conv fused with SSIM map + global reduction, ZB-blocked.
__global__ void pass3_kernel(int D, int lvl, W11 wt) {
    const int m = D - 10;
    const size_t plane = (size_t)m * m;
    const size_t planev = plane >> 1;
    const int nzb = (m + ZB - 1) / ZB;
    const size_t total = (size_t)2 * nzb * planev;
    size_t idx = (size_t)blockIdx.x * blockDim.x + threadIdx.x;
    float cs_t = 0.f, ss_t = 0.f;
    if (idx < total) {
        size_t xyv = idx % planev;
        size_t t = idx / planev;
        int zb = (int)(t % nzb);
        int n  = (int)(t / nzb);
        int z0 = zb * ZB;
        const size_t S2v = ((size_t)2 * D * plane) >> 1;
        const float2* in = (const float2*)g_T2;
        size_t b0 = (size_t)(n * D + z0) * planev + xyv;

        float2 acc[5][ZB];
#pragma unroll
        for (int f = 0; f < 5; f++)
#pragma unroll
            for (int j = 0; j < ZB; j++) acc[f][j] = make_float2(0.f, 0.f);

#pragma unroll
        for (int k = 0; k < ZB + 10; k++) {
            if (z0 + k < D) {
                float2 v[5];
#pragma unroll
                for (int f = 0; f < 5; f++) v[f] = in[f * S2v + b0 + (size_t)k * planev];
#pragma unroll
                for (int j = 0; j < ZB; j++) {
                    int ki = k - j;
                    if (ki >= 0 && ki < 11) {
                        float w = wt.w[ki];
#pragma unroll
                        for (int f = 0; f < 5; f++) {
                            acc[f][j].x = fmaf(w, v[f].x, acc[f][j].x);
                            acc[f][j].y = fmaf(w, v[f].y, acc[f][j].y);
                        }
                    }
                }
            }
        }

        float mx = dec_f(g_max_enc[lvl]);
        float mn = dec_f(g_min_enc[lvl]);
        float L  = (mx > 128.f ? 255.f : 1.f) - (mn < -0.5f ? -1.f : 0.f);
        float C1 = (0.01f * L) * (0.01f * L);
        float C2 = (0.03f * L) * (0.03f * L);
#pragma unroll
        for (int j = 0; j < ZB; j++) {
            if (z0 + j < m) {
                ssim_eval(acc[0][j].x, acc[1][j].x, acc[2][j].x, acc[3][j].x, acc[4][j].x,
                          C1, C2, cs_t, ss_t);
                ssim_eval(acc[0][j].y, acc[1][j].y, acc[2][j].y, acc[3][j].y, acc[4][j].y,
                          C1, C2, cs_t, ss_t);
            }
        }
    }
#pragma unroll
    for (int o = 16; o; o >>= 1) {
        cs_t += __shfl_xor_sync(0xFFFFFFFFu, cs_t, o);
        ss_t += __shfl_xor_sync(0xFFFFFFFFu, ss_t, o);
    }
    __shared__ float scs[8], sss[8];
    int w = threadIdx.x >> 5;
    if ((threadIdx.x & 31) == 0) { scs[w] = cs_t; sss[w] = ss_t; }
    __syncthreads();
    if (threadIdx.x == 0) {
        float c = 0.f, s = 0.f;
        int nw = blockDim.x >> 5;
        for (int i = 0; i < nw; i++) { c += scs[i]; s += sss[i]; }
        atomicAdd(&g_cs_sum[lvl], (double)c);
        atomicAdd(&g_ssim_sum[lvl], (double)s);
    }
}

// Pools BOTH volumes (A and B) in one launch: idx < total -> A, else B.
__global__ void pool_kernel(const float* __restrict__ inA, float* __restrict__ outA,
                            const float* __restrict__ inB, float* __restrict__ outB, int D) {
    const int Dh = D >> 1;
    size_t total = (size_t)2 * Dh * Dh * Dh;
    size_t gidx = (size_t)blockIdx.x * blockDim.x + threadIdx.x;
    const float* in;
    float* out;
    size_t idx;
    if (gidx < total) { in = inA; out = outA; idx = gidx; }
    else if (gidx < 2 * total) { in = inB; out = outB; idx = gidx - total; }
    else return;
    int x = (int)(idx % Dh);
    size_t t = idx / Dh;
    int y = (int)(t % Dh); t /= Dh;
    int z = (int)(t % Dh);
    int n = (int)(t / Dh);
    size_t pl = (size_t)D * D;
    const float* p = in + (size_t)(n * D + 2 * z) * pl + (size_t)(2 * y) * D + 2 * x;
    float s = p[0] + p[1] + p[D] + p[D + 1] + p[pl] + p[pl + 1] + p[pl + D] + p[pl + D + 1];
    out[idx] = 0.125f * s;
}

__global__ void final_kernel(float* out) {
    const float wts[5] = {0.0448f, 0.2856f, 0.3001f, 0.2363f, 0.1333f};
    const int dm[5] = {182, 86, 38, 14, 2};
    float r = 1.f;
    for (int i = 0; i < 5; i++) {
        double cnt = 2.0 * (double)dm[i] * (double)dm[i] * (double)dm[i];
        float v = (i < 4) ? (float)(g_cs_sum[i] / cnt) : (float)(g_ssim_sum[i] / cnt);
        r *= powf(v, wts[i]);
    }
    out[0] = r;
}

extern "C" void kernel_launch(void* const* d_in, const int* in_sizes, int n_in,
                              void* d_out, int out_size) {
    const float* A = (const float*)d_in[0];
    const float* B = (const float*)d_in[1];

    W11 wt;
    {
        double e[11], s = 0.0;
        for (int i = 0; i < 11; i++) {
            double d = (double)(i - 5);
            e[i] = exp(-(d * d) / 4.5);
            s += e[i];
        }
        for (int i = 0; i < 11; i++) wt.w[i] = (float)(e[i] / s);
    }

    float *poolA = nullptr, *poolB = nullptr;
    cudaGetSymbolAddress((void**)&poolA, g_poolA);
    cudaGetSymbolAddress((void**)&poolB, g_poolB);

    init_kernel<<<1, 32>>>();

    int D = 192;
    const float *cA = A, *cB = B;
    for (int lvl = 0; lvl < 5; lvl++) {
        int bdim = ((D + 31) / 32) * 32;
        pass1_kernel<<<2 * D * D, bdim>>>(cA, cB, D, lvl, wt);

        int Hm = D - 10, Wmv = (D - 10) >> 1;
        int nyb = (Hm + YB - 1) / YB;
        size_t t2 = (size_t)2 * D * nyb * Wmv;
        pass2_kernel<<<(unsigned)((t2 + 255) / 256), 256>>>(D, wt);

        int m = D - 10;
        int nzb = (m + ZB - 1) / ZB;
        size_t t3 = (size_t)2 * nzb * (((size_t)m * m) >> 1);
        pass3_kernel<<<(unsigned)((t3 + 255) / 256), 256>>>(D, lvl, wt);

        if (lvl < 4) {
            int Dh = D >> 1;
            size_t tp = (size_t)4 * Dh * Dh * Dh;   // both volumes
            unsigned gp = (unsigned)((tp + 255) / 256);
            float* nA = poolA + (size_t)(lvl & 1) * POOLSZ;
            float* nB = poolB + (size_t)(lvl & 1) * POOLSZ;
            pool_kernel<<<gp, 256>>>(cA, nA, cB, nB, D);
            cA = nA; cB = nB; D = Dh;
        }
    }

    final_kernel<<<1, 1>>>((float*)d_out);
}

// round 9
// speedup vs baseline: 1.0806x; 1.0806x over previous
#include <cuda_runtime.h>
#include <cuda_fp16.h>
#include <math.h>

// MS-SSIM 3D, 5 levels, separable 11-tap Gaussian conv.
// Intermediates (T1, T2) stored fp16 (compute fp32) to halve traffic and make
// T2 L2-resident. Inputs: d_in[0]=img1 (2,1,192,192,192) f32, d_in[1]=img2.

struct W11 { float w[11]; };

#define NLVL 5
#define ZB 8
#define YB 8

__device__ double   g_ssim_sum[NLVL];
__device__ double   g_cs_sum[NLVL];
__device__ unsigned g_min_enc[NLVL];
__device__ unsigned g_max_enc[NLVL];

#define S1MAX (2*192*192*182)   // elements per field after x-conv
#define S2MAX (2*192*182*182)   // elements per field after y-conv
#define POOLSZ (2*96*96*96)

__device__ __align__(16) __half g_T1[5ull * S1MAX];
__device__ __align__(16) __half g_T2[5ull * S2MAX];
__device__ __align__(16) float  g_poolA[2ull * POOLSZ];
__device__ __align__(16) float  g_poolB[2ull * POOLSZ];

__device__ __forceinline__ unsigned enc_f(float f) {
    unsigned u = __float_as_uint(f);
    return (u & 0x80000000u) ? ~u : (u | 0x80000000u);
}
__device__ __forceinline__ float dec_f(unsigned e) {
    unsigned u = (e & 0x80000000u) ? (e & 0x7FFFFFFFu) : ~e;
    return __uint_as_float(u);
}

__global__ void init_kernel() {
    int i = threadIdx.x;
    if (i < NLVL) {
        g_ssim_sum[i] = 0.0;
        g_cs_sum[i]   = 0.0;
        g_min_enc[i]  = 0xFFFFFFFFu;
        g_max_enc[i]  = 0u;
    }
}

// x-direction conv; builds all 5 fields (a, b, a*a, b*b, a*b) on the fly.
// Also folds the img1 min/max reduction (for L) into this pass.
__global__ void pass1_kernel(const float* __restrict__ A, const float* __restrict__ B,
                             int D, int lvl, W11 wt) {
    const int W = D, Wm = W - 10;
    const int row = blockIdx.x;
    __shared__ float sa[192], sb[192];
    const int tx = threadIdx.x;
    const float* a = A + (size_t)row * W;
    const float* b = B + (size_t)row * W;
    float av = 0.f;
    bool in_row = (tx < W);
    if (in_row) { av = a[tx]; sa[tx] = av; sb[tx] = b[tx]; }
    __syncthreads();

    // --- min/max reduction of A over this row ---
    unsigned mn = in_row ? enc_f(av) : 0xFFFFFFFFu;
    unsigned mx = in_row ? enc_f(av) : 0u;
#pragma unroll
    for (int o = 16; o; o >>= 1) {
        mn = min(mn, __shfl_xor_sync(0xFFFFFFFFu, mn, o));
        mx = max(mx, __shfl_xor_sync(0xFFFFFFFFu, mx, o));
    }
    __shared__ unsigned smn[6], smx[6];
    int wid = tx >> 5;
    if ((tx & 31) == 0) { smn[wid] = mn; smx[wid] = mx; }
    __syncthreads();
    if (tx == 0) {
        int nw = (blockDim.x + 31) >> 5;
        for (int i = 1; i < nw; i++) { mn = min(mn, smn[i]); mx = max(mx, smx[i]); }
        atomicMin(&g_min_enc[lvl], mn);
        atomicMax(&g_max_enc[lvl], mx);
    }

    // --- x-conv ---
    if (tx < Wm) {
        float s1 = 0.f, s2 = 0.f, s11 = 0.f, s22 = 0.f, s12 = 0.f;
#pragma unroll
        for (int k = 0; k < 11; k++) {
            float w = wt.w[k], x = sa[tx + k], y = sb[tx + k];
            s1  = fmaf(w, x, s1);
            s2  = fmaf(w, y, s2);
            float wx = w * x;
            s11 = fmaf(wx, x, s11);
            s12 = fmaf(wx, y, s12);
            s22 = fmaf(w * y, y, s22);
        }
        size_t S1 = (size_t)2 * D * D * Wm;
        size_t o  = (size_t)row * Wm + tx;
        g_T1[o]          = __float2half_rn(s1);
        g_T1[S1 + o]     = __float2half_rn(s2);
        g_T1[2 * S1 + o] = __float2half_rn(s11);
        g_T1[3 * S1 + o] = __float2half_rn(s22);
        g_T1[4 * S1 + o] = __float2half_rn(s12);
    }
}

// y-direction conv, half2 vectorized, YB-blocked, fp32 accumulation.
__global__ void pass2_kernel(int D, W11 wt) {
    const int Wm = D - 10, Hm = D - 10, Wmv = Wm >> 1;
    const int nyb = (Hm + YB - 1) / YB;
    const size_t S1v = ((size_t)2 * D * D * Wm) >> 1;
    const size_t S2v = ((size_t)2 * D * Hm * Wm) >> 1;
    const size_t total = (size_t)2 * D * nyb * Wmv;
    size_t idx = (size_t)blockIdx.x * blockDim.x + threadIdx.x;
    if (idx >= total) return;
    int xv = (int)(idx % Wmv);
    size_t t = idx / Wmv;
    int yb = (int)(t % nyb);
    int zn = (int)(t / nyb);           // 0 .. 2*D-1 (n*D + z)
    int y0 = yb * YB;
    const __half2* in  = (const __half2*)g_T1;
    __half2*       out = (__half2*)g_T2;
    size_t ib = ((size_t)zn * D + y0) * Wmv + xv;

    float2 acc[5][YB];
#pragma unroll
    for (int f = 0; f < 5; f++)
#pragma unroll
        for (int j = 0; j < YB; j++) acc[f][j] = make_float2(0.f, 0.f);

#pragma unroll
    for (int k = 0; k < YB + 10; k++) {
        if (y0 + k < D) {
            float2 v[5];
#pragma unroll
            for (int f = 0; f < 5; f++) v[f] = __half22float2(in[f * S1v + ib + (size_t)k * Wmv]);
#pragma unroll
            for (int j = 0; j < YB; j++) {
                int ki = k - j;
                if (ki >= 0 && ki < 11) {
                    float w = wt.w[ki];
#pragma unroll
                    for (int f = 0; f < 5; f++) {
                        acc[f][j].x = fmaf(w, v[f].x, acc[f][j].x);
                        acc[f][j].y = fmaf(w, v[f].y, acc[f][j].y);
                    }
                }
            }
        }
    }

#pragma unroll
    for (int j = 0; j < YB; j++) {
        if (y0 + j < Hm) {
            size_t ob = ((size_t)zn * Hm + (y0 + j)) * Wmv + xv;
#pragma unroll
            for (int f = 0; f < 5; f++)
                out[f * S2v + ob] = __floats2half2_rn(acc[f][j].x, acc[f][j].y);
        }
    }
}

__device__ __forceinline__ void ssim_eval(float m1, float m2, float q11, float q22, float q12,
                                          float C1, float C2, float& cs_acc, float& ss_acc) {
    float mu11 = m1 * m1, mu22 = m2 * m2, mu12 = m1 * m2;
    float sg1 = q11 - mu11, sg2 = q22 - mu22, sg12 = q12 - mu12;
    float v1 = 2.f * sg12 + C2;
    float v2 = sg1 + sg2 + C2;
    cs_acc += v1 / v2;
    ss_acc += ((2.f * mu12 + C1) * v1) / ((mu11 + mu22 + C1) * v2);
}

// z-direction conv fused with SSIM map + global reduction, ZB-blocked.
__global__ void pass3_kernel(int D, int lvl, W11 wt) {
    const int m = D - 10;
    const size_t plane = (size_t)m * m;
    const size_t planev = plane >> 1;
    const int nzb = (m + ZB - 1) / ZB;
    const size_t total = (size_t)2 * nzb * planev;
    size_t idx = (size_t)blockIdx.x * blockDim.x + threadIdx.x;
    float cs_t = 0.f, ss_t = 0.f;
    if (idx < total) {
        size_t xyv = idx % planev;
        size_t t = idx / planev;
        int zb = (int)(t % nzb);
        int n  = (int)(t / nzb);
        int z0 = zb * ZB;
        const size_t S2v = ((size_t)2 * D * plane) >> 1;
        const __half2* in = (const __half2*)g_T2;
        size_t b0 = (size_t)(n * D + z0) * planev + xyv;

        float2 acc[5][ZB];
#pragma unroll
        for (int f = 0; f < 5; f++)
#pragma unroll
            for (int j = 0; j < ZB; j++) acc[f][j] = make_float2(0.f, 0.f);

#pragma unroll
        for (int k = 0; k < ZB + 10; k++) {
            if (z0 + k < D) {
                float2 v[5];
#pragma unroll
                for (int f = 0; f < 5; f++) v[f] = __half22float2(in[f * S2v + b0 + (size_t)k * planev]);
#pragma unroll
                for (int j = 0; j < ZB; j++) {
                    int ki = k - j;
                    if (ki >= 0 && ki < 11) {
                        float w = wt.w[ki];
#pragma unroll
                        for (int f = 0; f < 5; f++) {
                            acc[f][j].x = fmaf(w, v[f].x, acc[f][j].x);
                            acc[f][j].y = fmaf(w, v[f].y, acc[f][j].y);
                        }
                    }
                }
            }
        }

        float mx = dec_f(g_max_enc[lvl]);
        float mn = dec_f(g_min_enc[lvl]);
        float L  = (mx > 128.f ? 255.f : 1.f) - (mn < -0.5f ? -1.f : 0.f);
        float C1 = (0.01f * L) * (0.01f * L);
        float C2 = (0.03f * L) * (0.03f * L);
#pragma unroll
        for (int j = 0; j < ZB; j++) {
            if (z0 + j < m) {
                ssim_eval(acc[0][j].x, acc[1][j].x, acc[2][j].x, acc[3][j].x, acc[4][j].x,
                          C1, C2, cs_t, ss_t);
                ssim_eval(acc[0][j].y, acc[1][j].y, acc[2][j].y, acc[3][j].y, acc[4][j].y,
                          C1, C2, cs_t, ss_t);
            }
        }
    }
#pragma unroll
    for (int o = 16; o; o >>= 1) {
        cs_t += __shfl_xor_sync(0xFFFFFFFFu, cs_t, o);
        ss_t += __shfl_xor_sync(0xFFFFFFFFu, ss_t, o);
    }
    __shared__ float scs[8], sss[8];
    int w = threadIdx.x >> 5;
    if ((threadIdx.x & 31) == 0) { scs[w] = cs_t; sss[w] = ss_t; }
    __syncthreads();
    if (threadIdx.x == 0) {
        float c = 0.f, s = 0.f;
        int nw = blockDim.x >> 5;
        for (int i = 0; i < nw; i++) { c += scs[i]; s += sss[i]; }
        atomicAdd(&g_cs_sum[lvl], (double)c);
        atomicAdd(&g_ssim_sum[lvl], (double)s);
    }
}

// Pools BOTH volumes (A and B) in one launch: idx < total -> A, else B.
__global__ void pool_kernel(const float* __restrict__ inA, float* __restrict__ outA,
                            const float* __restrict__ inB, float* __restrict__ outB, int D) {
    const int Dh = D >> 1;
    size_t total = (size_t)2 * Dh * Dh * Dh;
    size_t gidx = (size_t)blockIdx.x * blockDim.x + threadIdx.x;
    const float* in;
    float* out;
    size_t idx;
    if (gidx < total) { in = inA; out = outA; idx = gidx; }
    else if (gidx < 2 * total) { in = inB; out = outB; idx = gidx - total; }
    else return;
    int x = (int)(idx % Dh);
    size_t t = idx / Dh;
    int y = (int)(t % Dh); t /= Dh;
    int z = (int)(t % Dh);
    int n = (int)(t / Dh);
    size_t pl = (size_t)D * D;
    const float* p = in + (size_t)(n * D + 2 * z) * pl + (size_t)(2 * y) * D + 2 * x;
    float s = p[0] + p[1] + p[D] + p[D + 1] + p[pl] + p[pl + 1] + p[pl + D] + p[pl + D + 1];
    out[idx] = 0.125f * s;
}

__global__ void final_kernel(float* out) {
    const float wts[5] = {0.0448f, 0.2856f, 0.3001f, 0.2363f, 0.1333f};
    const int dm[5] = {182, 86, 38, 14, 2};
    float r = 1.f;
    for (int i = 0; i < 5; i++) {
        double cnt = 2.0 * (double)dm[i] * (double)dm[i] * (double)dm[i];
        float v = (i < 4) ? (float)(g_cs_sum[i] / cnt) : (float)(g_ssim_sum[i] / cnt);
        r *= powf(v, wts[i]);
    }
    out[0] = r;
}

extern "C" void kernel_launch(void* const* d_in, const int* in_sizes, int n_in,
                              void* d_out, int out_size) {
    const float* A = (const float*)d_in[0];
    const float* B = (const float*)d_in[1];

    W11 wt;
    {
        double e[11], s = 0.0;
        for (int i = 0; i < 11; i++) {
            double d = (double)(i - 5);
            e[i] = exp(-(d * d) / 4.5);
            s += e[i];
        }
        for (int i = 0; i < 11; i++) wt.w[i] = (float)(e[i] / s);
    }

    float *poolA = nullptr, *poolB = nullptr;
    cudaGetSymbolAddress((void**)&poolA, g_poolA);
    cudaGetSymbolAddress((void**)&poolB, g_poolB);

    init_kernel<<<1, 32>>>();

    int D = 192;
    const float *cA = A, *cB = B;
    for (int lvl = 0; lvl < 5; lvl++) {
        int bdim = ((D + 31) / 32) * 32;
        pass1_kernel<<<2 * D * D, bdim>>>(cA, cB, D, lvl, wt);

        int Hm = D - 10, Wmv = (D - 10) >> 1;
        int nyb = (Hm + YB - 1) / YB;
        size_t t2 = (size_t)2 * D * nyb * Wmv;
        pass2_kernel<<<(unsigned)((t2 + 255) / 256), 256>>>(D, wt);

        int m = D - 10;
        int nzb = (m + ZB - 1) / ZB;
        size_t t3 = (size_t)2 * nzb * (((size_t)m * m) >> 1);
        pass3_kernel<<<(unsigned)((t3 + 255) / 256), 256>>>(D, lvl, wt);

        if (lvl < 4) {
            int Dh = D >> 1;
            size_t tp = (size_t)4 * Dh * Dh * Dh;   // both volumes
            unsigned gp = (unsigned)((tp + 255) / 256);
            float* nA = poolA + (size_t)(lvl & 1) * POOLSZ;
            float* nB = poolB + (size_t)(lvl & 1) * POOLSZ;
            pool_kernel<<<gp, 256>>>(cA, nA, cB, nB, D);
            cA = nA; cB = nB; D = Dh;
        }
    }

    final_kernel<<<1, 1>>>((float*)d_out);
}

// round 16
// speedup vs baseline: 1.2028x; 1.1130x over previous
#include <cuda_runtime.h>
#include <cuda_fp16.h>
#include <math.h>

// MS-SSIM 3D, 5 levels, separable 11-tap Gaussian conv.
// Intermediates stored field-interleaved: one uint4 (16B) per spatial position
// holding 5 fp16 fields (+3 pad). One LDG.128 replaces 5 scattered loads.

struct W11 { float w[11]; };

#define NLVL 5
#define ZB 8
#define YB 8

__device__ double   g_ssim_sum[NLVL];
__device__ double   g_cs_sum[NLVL];
__device__ unsigned g_min_enc[NLVL];
__device__ unsigned g_max_enc[NLVL];

#define S1MAX (2*192*192*182)   // positions after x-conv
#define S2MAX (2*192*182*182)   // positions after y-conv
#define POOLSZ (2*96*96*96)

__device__ __align__(16) uint4 g_T1[S1MAX];
__device__ __align__(16) uint4 g_T2[S2MAX];
__device__ __align__(16) float g_poolA[2ull * POOLSZ];
__device__ __align__(16) float g_poolB[2ull * POOLSZ];

__device__ __forceinline__ unsigned enc_f(float f) {
    unsigned u = __float_as_uint(f);
    return (u & 0x80000000u) ? ~u : (u | 0x80000000u);
}
__device__ __forceinline__ float dec_f(unsigned e) {
    unsigned u = (e & 0x80000000u) ? (e & 0x7FFFFFFFu) : ~e;
    return __uint_as_float(u);
}

__device__ __forceinline__ uint4 pack5(float a, float b, float c, float d, float e) {
    uint4 r;
    __half2 p0 = __floats2half2_rn(a, b);
    __half2 p1 = __floats2half2_rn(c, d);
    __half2 p2 = __floats2half2_rn(e, 0.f);
    r.x = *(unsigned*)&p0;
    r.y = *(unsigned*)&p1;
    r.z = *(unsigned*)&p2;
    r.w = 0u;
    return r;
}
__device__ __forceinline__ void unpack5(uint4 r, float v[5]) {
    float2 p0 = __half22float2(*(__half2*)&r.x);
    float2 p1 = __half22float2(*(__half2*)&r.y);
    float2 p2 = __half22float2(*(__half2*)&r.z);
    v[0] = p0.x; v[1] = p0.y; v[2] = p1.x; v[3] = p1.y; v[4] = p2.x;
}

__global__ void init_kernel() {
    int i = threadIdx.x;
    if (i < NLVL) {
        g_ssim_sum[i] = 0.0;
        g_cs_sum[i]   = 0.0;
        g_min_enc[i]  = 0xFFFFFFFFu;
        g_max_enc[i]  = 0u;
    }
}

// x-direction conv; builds all 5 fields (a, b, a*a, b*b, a*b) on the fly.
// Also folds the img1 min/max reduction (for L) into this pass.
__global__ void pass1_kernel(const float* __restrict__ A, const float* __restrict__ B,
                             int D, int lvl, W11 wt) {
    const int W = D, Wm = W - 10;
    const int row = blockIdx.x;
    __shared__ float sa[192], sb[192];
    const int tx = threadIdx.x;
    const float* a = A + (size_t)row * W;
    const float* b = B + (size_t)row * W;
    float av = 0.f;
    bool in_row = (tx < W);
    if (in_row) { av = a[tx]; sa[tx] = av; sb[tx] = b[tx]; }
    __syncthreads();

    // --- min/max reduction of A over this row ---
    unsigned mn = in_row ? enc_f(av) : 0xFFFFFFFFu;
    unsigned mx = in_row ? enc_f(av) : 0u;
#pragma unroll
    for (int o = 16; o; o >>= 1) {
        mn = min(mn, __shfl_xor_sync(0xFFFFFFFFu, mn, o));
        mx = max(mx, __shfl_xor_sync(0xFFFFFFFFu, mx, o));
    }
    __shared__ unsigned smn[6], smx[6];
    int wid = tx >> 5;
    if ((tx & 31) == 0) { smn[wid] = mn; smx[wid] = mx; }
    __syncthreads();
    if (tx == 0) {
        int nw = (blockDim.x + 31) >> 5;
        for (int i = 1; i < nw; i++) { mn = min(mn, smn[i]); mx = max(mx, smx[i]); }
        atomicMin(&g_min_enc[lvl], mn);
        atomicMax(&g_max_enc[lvl], mx);
    }

    // --- x-conv ---
    if (tx < Wm) {
        float s1 = 0.f, s2 = 0.f, s11 = 0.f, s22 = 0.f, s12 = 0.f;
#pragma unroll
        for (int k = 0; k < 11; k++) {
            float w = wt.w[k], x = sa[tx + k], y = sb[tx + k];
            s1  = fmaf(w, x, s1);
            s2  = fmaf(w, y, s2);
            float wx = w * x;
            s11 = fmaf(wx, x, s11);
            s12 = fmaf(wx, y, s12);
            s22 = fmaf(w * y, y, s22);
        }
        g_T1[(size_t)row * Wm + tx] = pack5(s1, s2, s11, s22, s12);
    }
}

// y-direction conv, YB-blocked, interleaved 16B loads/stores, fp32 accumulation.
__global__ void pass2_kernel(int D, W11 wt) {
    const int Wm = D - 10, Hm = D - 10;
    const int nyb = (Hm + YB - 1) / YB;
    const size_t total = (size_t)2 * D * nyb * Wm;
    size_t idx = (size_t)blockIdx.x * blockDim.x + threadIdx.x;
    if (idx >= total) return;
    int x = (int)(idx % Wm);
    size_t t = idx / Wm;
    int yb = (int)(t % nyb);
    int zn = (int)(t / nyb);           // 0 .. 2*D-1 (n*D + z)
    int y0 = yb * YB;
    size_t ib = ((size_t)zn * D + y0) * Wm + x;

    float acc[5][YB];
#pragma unroll
    for (int f = 0; f < 5; f++)
#pragma unroll
        for (int j = 0; j < YB; j++) acc[f][j] = 0.f;

#pragma unroll
    for (int k = 0; k < YB + 10; k++) {
        if (y0 + k < D) {
            float v[5];
            unpack5(g_T1[ib + (size_t)k * Wm], v);
#pragma unroll
            for (int j = 0; j < YB; j++) {
                int ki = k - j;
                if (ki >= 0 && ki < 11) {
                    float w = wt.w[ki];
#pragma unroll
                    for (int f = 0; f < 5; f++) acc[f][j] = fmaf(w, v[f], acc[f][j]);
                }
            }
        }
    }

#pragma unroll
    for (int j = 0; j < YB; j++) {
        if (y0 + j < Hm) {
            size_t ob = ((size_t)zn * Hm + (y0 + j)) * Wm + x;
            g_T2[ob] = pack5(acc[0][j], acc[1][j], acc[2][j], acc[3][j], acc[4][j]);
        }
    }
}

__device__ __forceinline__ void ssim_eval(float m1, float m2, float q11, float q22, float q12,
                                          float C1, float C2, float& cs_acc, float& ss_acc) {
    float mu11 = m1 * m1, mu22 = m2 * m2, mu12 = m1 * m2;
    float sg1 = q11 - mu11, sg2 = q22 - mu22, sg12 = q12 - mu12;
    float v1 = 2.f * sg12 + C2;
    float v2 = sg1 + sg2 + C2;
    cs_acc += v1 / v2;
    ss_acc += ((2.f * mu12 + C1) * v1) / ((mu11 + mu22 + C1) * v2);
}

// z-direction conv fused with SSIM map + global reduction, ZB-blocked.
__global__ void pass3_kernel(int D, int lvl, W11 wt) {
    const int m = D - 10;
    const size_t plane = (size_t)m * m;
    const int nzb = (m + ZB - 1) / ZB;
    const size_t total = (size_t)2 * nzb * plane;
    size_t idx = (size_t)blockIdx.x * blockDim.x + threadIdx.x;
    float cs_t = 0.f, ss_t = 0.f;
    if (idx < total) {
        size_t xy = idx % plane;
        size_t t = idx / plane;
        int zb = (int)(t % nzb);
        int n  = (int)(t / nzb);
        int z0 = zb * ZB;
        size_t b0 = ((size_t)n * D + z0) * plane + xy;

        float acc[5][ZB];
#pragma unroll
        for (int f = 0; f < 5; f++)
#pragma unroll
            for (int j = 0; j < ZB; j++) acc[f][j] = 0.f;

#pragma unroll
        for (int k = 0; k < ZB + 10; k++) {
            if (z0 + k < D) {
                float v[5];
                unpack5(g_T2[b0 + (size_t)k * plane], v);
#pragma unroll
                for (int j = 0; j < ZB; j++) {
                    int ki = k - j;
                    if (ki >= 0 && ki < 11) {
                        float w = wt.w[ki];
#pragma unroll
                        for (int f = 0; f < 5; f++) acc[f][j] = fmaf(w, v[f], acc[f][j]);
                    }
                }
            }
        }

        float mx = dec_f(g_max_enc[lvl]);
        float mn = dec_f(g_min_enc[lvl]);
        float L  = (mx > 128.f ? 255.f : 1.f) - (mn < -0.5f ? -1.f : 0.f);
        float C1 = (0.01f * L) * (0.01f * L);
        float C2 = (0.03f * L) * (0.03f * L);
#pragma unroll
        for (int j = 0; j < ZB; j++) {
            if (z0 + j < m) {
                ssim_eval(acc[0][j], acc[1][j], acc[2][j], acc[3][j], acc[4][j],
                          C1, C2, cs_t, ss_t);
            }
        }
    }
#pragma unroll
    for (int o = 16; o; o >>= 1) {
        cs_t += __shfl_xor_sync(0xFFFFFFFFu, cs_t, o);
        ss_t += __shfl_xor_sync(0xFFFFFFFFu, ss_t, o);
    }
    __shared__ float scs[8], sss[8];
    int w = threadIdx.x >> 5;
    if ((threadIdx.x & 31) == 0) { scs[w] = cs_t; sss[w] = ss_t; }
    __syncthreads();
    if (threadIdx.x == 0) {
        float c = 0.f, s = 0.f;
        int nw = blockDim.x >> 5;
        for (int i = 0; i < nw; i++) { c += scs[i]; s += sss[i]; }
        atomicAdd(&g_cs_sum[lvl], (double)c);
        atomicAdd(&g_ssim_sum[lvl], (double)s);
    }
}

// Pools BOTH volumes (A and B) in one launch: idx < total -> A, else B.
__global__ void pool_kernel(const float* __restrict__ inA, float* __restrict__ outA,
                            const float* __restrict__ inB, float* __restrict__ outB, int D) {
    const int Dh = D >> 1;
    size_t total = (size_t)2 * Dh * Dh * Dh;
    size_t gidx = (size_t)blockIdx.x * blockDim.x + threadIdx.x;
    const float* in;
    float* out;
    size_t idx;
    if (gidx < total) { in = inA; out = outA; idx = gidx; }
    else if (gidx < 2 * total) { in = inB; out = outB; idx = gidx - total; }
    else return;
    int x = (int)(idx % Dh);
    size_t t = idx / Dh;
    int y = (int)(t % Dh); t /= Dh;
    int z = (int)(t % Dh);
    int n = (int)(t / Dh);
    size_t pl = (size_t)D * D;
    const float* p = in + (size_t)(n * D + 2 * z) * pl + (size_t)(2 * y) * D + 2 * x;
    float s = p[0] + p[1] + p[D] + p[D + 1] + p[pl] + p[pl + 1] + p[pl + D] + p[pl + D + 1];
    out[idx] = 0.125f * s;
}

__global__ void final_kernel(float* out) {
    const float wts[5] = {0.0448f, 0.2856f, 0.3001f, 0.2363f, 0.1333f};
    const int dm[5] = {182, 86, 38, 14, 2};
    float r = 1.f;
    for (int i = 0; i < 5; i++) {
        double cnt = 2.0 * (double)dm[i] * (double)dm[i] * (double)dm[i];
        float v = (i < 4) ? (float)(g_cs_sum[i] / cnt) : (float)(g_ssim_sum[i] / cnt);
        r *= powf(v, wts[i]);
    }
    out[0] = r;
}

extern "C" void kernel_launch(void* const* d_in, const int* in_sizes, int n_in,
                              void* d_out, int out_size) {
    const float* A = (const float*)d_in[0];
    const float* B = (const float*)d_in[1];

    W11 wt;
    {
        double e[11], s = 0.0;
        for (int i = 0; i < 11; i++) {
            double d = (double)(i - 5);
            e[i] = exp(-(d * d) / 4.5);
            s += e[i];
        }
        for (int i = 0; i < 11; i++) wt.w[i] = (float)(e[i] / s);
    }

    float *poolA = nullptr, *poolB = nullptr;
    cudaGetSymbolAddress((void**)&poolA, g_poolA);
    cudaGetSymbolAddress((void**)&poolB, g_poolB);

    init_kernel<<<1, 32>>>();

    int D = 192;
    const float *cA = A, *cB = B;
    for (int lvl = 0; lvl < 5; lvl++) {
        int bdim = ((D + 31) / 32) * 32;
        pass1_kernel<<<2 * D * D, bdim>>>(cA, cB, D, lvl, wt);

        int Hm = D - 10, Wm = D - 10;
        int nyb = (Hm + YB - 1) / YB;
        size_t t2 = (size_t)2 * D * nyb * Wm;
        pass2_kernel<<<(unsigned)((t2 + 255) / 256), 256>>>(D, wt);

        int m = D - 10;
        int nzb = (m + ZB - 1) / ZB;
        size_t t3 = (size_t)2 * nzb * ((size_t)m * m);
        pass3_kernel<<<(unsigned)((t3 + 255) / 256), 256>>>(D, lvl, wt);

        if (lvl < 4) {
            int Dh = D >> 1;
            size_t tp = (size_t)4 * Dh * Dh * Dh;   // both volumes
            unsigned gp = (unsigned)((tp + 255) / 256);
            float* nA = poolA + (size_t)(lvl & 1) * POOLSZ;
            float* nB = poolB + (size_t)(lvl & 1) * POOLSZ;
            pool_kernel<<<gp, 256>>>(cA, nA, cB, nB, D);
            cA = nA; cB = nB; D = Dh;
        }
    }

    final_kernel<<<1, 1>>>((float*)d_out);
}